// round 15
// baseline (speedup 1.0000x reference)
#include <cuda_runtime.h>
#include <cuda_fp16.h>
#include <cstdint>

// Problem constants
constexpr int V_ = 20000;
constexpr int E_ = 300;
constexpr int EK_ = 320;      // E padded to BK multiple (zero-filled)
constexpr int H_ = 2400;
constexpr int B_ = 32;
constexpr int S_ = 64;
constexpr int M_ = B_ * S_;   // 2048
constexpr int G_ = 3 * H_;    // 7200

static_assert(EK_ % 32 == 0, "phase A K tiling");
static_assert(H_ % 48 == 0, "recurrence + phase C K tiling (BK=48)");

// Scratch (static device globals; no runtime allocation)
__device__ __half g_emb[(size_t)M_ * EK_];
__device__ float  g_xg[(size_t)M_ * G_];
__device__ __half g_hs[(size_t)M_ * H_];   // layout [b][s][H]
__device__ __half g_h0[B_ * H_];
__device__ __half g_h1[B_ * H_];
__device__ __half g_wih[(size_t)G_ * EK_];
__device__ __half g_whh[(size_t)G_ * H_];
__device__ __half g_wout[(size_t)V_ * H_];
__device__ float  g_bih[G_];
__device__ float  g_bhh[G_];

// ---------------------------------------------------------------------------
#define MMA_F16(c, a, b)                                                      \
    asm volatile(                                                             \
        "mma.sync.aligned.m16n8k16.row.col.f32.f16.f16.f32 "                  \
        "{%0,%1,%2,%3}, {%4,%5,%6,%7}, {%8,%9}, {%0,%1,%2,%3};\n"             \
        : "+f"((c)[0]), "+f"((c)[1]), "+f"((c)[2]), "+f"((c)[3])              \
        : "r"((a)[0]), "r"((a)[1]), "r"((a)[2]), "r"((a)[3]),                 \
          "r"((b)[0]), "r"((b)[1]))

__device__ __forceinline__ void ldsm_x4(uint32_t& r0, uint32_t& r1,
                                        uint32_t& r2, uint32_t& r3, uint32_t a) {
    asm volatile("ldmatrix.sync.aligned.m8n8.x4.shared.b16 {%0,%1,%2,%3}, [%4];"
                 : "=r"(r0), "=r"(r1), "=r"(r2), "=r"(r3) : "r"(a));
}
__device__ __forceinline__ void ldsm_x2(uint32_t& r0, uint32_t& r1, uint32_t a) {
    asm volatile("ldmatrix.sync.aligned.m8n8.x2.shared.b16 {%0,%1}, [%2];"
                 : "=r"(r0), "=r"(r1) : "r"(a));
}

// ---------------------------------------------------------------------------
// Pre-pass kernels
// ---------------------------------------------------------------------------
__global__ void prep_whh(const float* __restrict__ Whh) {
    size_t n = (size_t)G_ * H_;
    for (size_t i = (size_t)blockIdx.x * blockDim.x + threadIdx.x; i < n;
         i += (size_t)gridDim.x * blockDim.x) {
        int np = (int)(i / H_);
        int k = (int)(i - (size_t)np * H_);
        int j = np / 3, g = np % 3;
        g_whh[i] = __float2half_rn(Whh[(size_t)(g * H_ + j) * H_ + k]);
    }
}
__global__ void prep_wih_bias(const float* __restrict__ Wih,
                              const float* __restrict__ bih,
                              const float* __restrict__ bhh) {
    size_t n = (size_t)G_ * EK_;
    for (size_t i = (size_t)blockIdx.x * blockDim.x + threadIdx.x; i < n;
         i += (size_t)gridDim.x * blockDim.x) {
        int np = (int)(i / EK_);
        int k = (int)(i - (size_t)np * EK_);
        int j = np / 3, g = np % 3;
        g_wih[i] = (k < E_) ? __float2half_rn(Wih[(size_t)(g * H_ + j) * E_ + k])
                            : __half(0.f);
    }
    int t = blockIdx.x * blockDim.x + threadIdx.x;
    if (t < G_) {
        int j = t / 3, g = t % 3;
        g_bih[t] = bih[g * H_ + j];
        g_bhh[t] = bhh[g * H_ + j];
    }
}
__global__ void prep_wout(const float* __restrict__ Wout) {
    size_t n = (size_t)V_ * H_;
    for (size_t i = (size_t)blockIdx.x * blockDim.x + threadIdx.x; i < n;
         i += (size_t)gridDim.x * blockDim.x)
        g_wout[i] = __float2half_rn(Wout[i]);
}

__global__ void gather_init_kernel(const int* __restrict__ tgt,
                                   const float* __restrict__ emb_table,
                                   const float* __restrict__ sentence_vec) {
    int idx = blockIdx.x * blockDim.x + threadIdx.x;
    if (idx < M_ * EK_) {
        int m = idx / EK_;
        int e = idx - m * EK_;
        g_emb[idx] = (e < E_) ? __float2half_rn(emb_table[(size_t)tgt[m] * E_ + e])
                              : __half(0.f);
    }
    if (idx < B_ * H_) g_h0[idx] = __float2half_rn(sentence_vec[idx]);
}

// ---------------------------------------------------------------------------
// fp16 pipelined GEMM (HMMA m16n8k16 + ldmatrix).
//   C[m,n] = sum_k A[m,k]*B[n,k]  (+bias / fused GRU epilogue)
// EPI 0: C = acc + bias (fp32 out).  EPI 1: fused GRU update (BM=32).
// PERSIST: grid-stride loop over (m,n) tiles, m-fastest (phase C).
// Requires K % BK == 0.
// ---------------------------------------------------------------------------
template <int BM, int BN, int BK, int WM, int WN, int EPI, int STAGES, int PERSIST>
__global__ void __launch_bounds__((BM / WM) * (BN / WN) * 32)
gemm_f16(const __half* __restrict__ A, const __half* __restrict__ Bmat,
         const float* __restrict__ bias, float* __restrict__ C,
         int M, int N, int K,
         const float* __restrict__ xg, const __half* __restrict__ h_old,
         __half* __restrict__ h_new, __half* __restrict__ hs, int s) {
    constexpr int WARPS_M = BM / WM;
    constexpr int WARPS_N = BN / WN;
    constexpr int NT = WARPS_M * WARPS_N * 32;
    constexpr int MFRAG = WM / 16;
    constexpr int NFRAG = WN / 8;
    constexpr int LDH = BK + 8;
    constexpr int A_ST = BM * LDH;
    constexpr int B_ST = BN * LDH;
    constexpr int ST = A_ST + B_ST;

    extern __shared__ __half smbuf[];

    const int tid = threadIdx.x;
    const int warp = tid >> 5, lane = tid & 31;
    const int gr = lane >> 2, gc = lane & 3;
    const int wm = (warp % WARPS_M) * WM;
    const int wn = (warp / WARPS_M) * WN;

    const uint32_t sbase = (uint32_t)__cvta_generic_to_shared(smbuf);

    const int sub = lane >> 3, lr = lane & 7;
    const int a_off = ((sub & 1) * 8 + lr) * LDH + (sub >> 1) * 8;
    const int b_off = ((sub >> 1) * 8 + lr) * LDH + (sub & 1) * 8;
    const int b2_off = ((lane & 15) >> 3) * 8 + (lr)*LDH;

    const int T = K / BK;
    const int tiles_x = M / BM;
    const int tiles_y = (N + BN - 1) / BN;
    const int ntiles = PERSIST ? tiles_x * tiles_y : 1;

    for (int tile = blockIdx.x; tile < (PERSIST ? ntiles : (int)blockIdx.x + 1);
         tile += (PERSIST ? gridDim.x : 1)) {
        const int bm0 = PERSIST ? (tile % tiles_x) * BM : blockIdx.x * BM;
        const int bn0 = PERSIST ? (tile / tiles_x) * BN : blockIdx.y * BN;

        // Protect smem stage reuse against warps still reading the previous
        // tile's last stages (prologue below rewrites stages 0..STAGES-2).
        if (PERSIST) __syncthreads();

        auto load_tile = [&](int stage, int t) {
            const uint32_t sA = sbase + stage * ST * 2;
            const uint32_t sB = sA + A_ST * 2;
            const int k0 = t * BK;
            constexpr int CHR = BK / 8;
            constexpr int CHA = BM * CHR;
#pragma unroll
            for (int c = tid; c < CHA; c += NT) {
                int row = c / CHR, ch = c % CHR;
                uint32_t dst = sA + (row * LDH + ch * 8) * 2;
                const __half* src = A + (size_t)(bm0 + row) * K + k0 + ch * 8;
                asm volatile("cp.async.cg.shared.global [%0], [%1], 16;\n" ::
                             "r"(dst), "l"(src));
            }
            constexpr int CHB = BN * CHR;
#pragma unroll
            for (int c = tid; c < CHB; c += NT) {
                int row = c / CHR, ch = c % CHR;
                int gn = bn0 + row;
                uint32_t dst = sB + (row * LDH + ch * 8) * 2;
                const __half* src = Bmat + (size_t)gn * K + k0 + ch * 8;
                int bytes = (gn < N) ? 16 : 0;
                asm volatile("cp.async.cg.shared.global [%0], [%1], 16, %2;\n" ::
                             "r"(dst), "l"(src), "r"(bytes));
            }
            asm volatile("cp.async.commit_group;\n");
        };

        float acc[MFRAG][NFRAG][4];
#pragma unroll
        for (int i = 0; i < MFRAG; i++)
#pragma unroll
            for (int j = 0; j < NFRAG; j++)
#pragma unroll
                for (int r = 0; r < 4; r++) acc[i][j][r] = 0.f;

        const int npre = (STAGES - 1 < T) ? STAGES - 1 : T;
        for (int t = 0; t < npre; t++) load_tile(t, t);

        for (int t = 0; t < T; t++) {
            asm volatile("cp.async.wait_group %0;\n" ::"n"(STAGES - 2));
            __syncthreads();
            if (t + STAGES - 1 < T) {
                load_tile((t + STAGES - 1) % STAGES, t + STAGES - 1);
            } else {
                asm volatile("cp.async.commit_group;\n");
            }
            const uint32_t sA = sbase + (t % STAGES) * ST * 2;
            const uint32_t sB = sA + A_ST * 2;
#pragma unroll
            for (int kk = 0; kk < BK; kk += 16) {
                uint32_t af[MFRAG][4];
#pragma unroll
                for (int i = 0; i < MFRAG; i++)
                    ldsm_x4(af[i][0], af[i][1], af[i][2], af[i][3],
                            sA + ((wm + i * 16) * LDH + kk + a_off) * 2);
                uint32_t bf[NFRAG][2];
#pragma unroll
                for (int j = 0; j + 1 < NFRAG; j += 2)
                    ldsm_x4(bf[j][0], bf[j][1], bf[j + 1][0], bf[j + 1][1],
                            sB + ((wn + j * 8) * LDH + kk + b_off) * 2);
                if (NFRAG & 1)
                    ldsm_x2(bf[NFRAG - 1][0], bf[NFRAG - 1][1],
                            sB + ((wn + (NFRAG - 1) * 8) * LDH + kk + b2_off) * 2);
#pragma unroll
                for (int i = 0; i < MFRAG; i++)
#pragma unroll
                    for (int j = 0; j < NFRAG; j++) MMA_F16(acc[i][j], af[i], bf[j]);
            }
        }

        if (EPI == 0) {
#pragma unroll
            for (int i = 0; i < MFRAG; i++)
#pragma unroll
                for (int j = 0; j < NFRAG; j++) {
                    int n = bn0 + wn + j * 8 + gc * 2;
#pragma unroll
                    for (int half_ = 0; half_ < 2; half_++) {
                        int m = bm0 + wm + i * 16 + gr + half_ * 8;
                        float v0 = acc[i][j][half_ * 2 + 0];
                        float v1 = acc[i][j][half_ * 2 + 1];
                        if (n < N)     C[(size_t)m * N + n]     = v0 + bias[n];
                        if (n + 1 < N) C[(size_t)m * N + n + 1] = v1 + bias[n + 1];
                    }
                }
        } else {
            // Fused GRU update. BM=32 (batch), BN=48 (16 hidden units x 3
            // gates, interleaved r,z,n). acc -> smem -> per-(b,j) update.
            __syncthreads();
            float* hg = (float*)smbuf;  // 32x48 floats (aliases stages)
#pragma unroll
            for (int i = 0; i < MFRAG; i++)
#pragma unroll
                for (int j = 0; j < NFRAG; j++) {
                    int m0 = wm + i * 16 + gr;
                    int n0 = wn + j * 8 + gc * 2;
                    hg[m0 * BN + n0]           = acc[i][j][0];
                    hg[m0 * BN + n0 + 1]       = acc[i][j][1];
                    hg[(m0 + 8) * BN + n0]     = acc[i][j][2];
                    hg[(m0 + 8) * BN + n0 + 1] = acc[i][j][3];
                }
            __syncthreads();
            const int jbase = bn0 / 3;
            for (int it = tid; it < B_ * (BN / 3); it += NT) {
                int b = it / (BN / 3);
                int lj = it % (BN / 3);
                int jg = jbase + lj;
                float hr = hg[b * BN + 3 * lj + 0] + bias[bn0 + 3 * lj + 0];
                float hz = hg[b * BN + 3 * lj + 1] + bias[bn0 + 3 * lj + 1];
                float hnn = hg[b * BN + 3 * lj + 2] + bias[bn0 + 3 * lj + 2];
                const float* xrow = xg + (size_t)(b * S_ + s) * G_ + bn0 + 3 * lj;
                float xr = xrow[0], xz = xrow[1], xn = xrow[2];
                float r = 1.f / (1.f + expf(-(xr + hr)));
                float z = 1.f / (1.f + expf(-(xz + hz)));
                float nn = tanhf(xn + r * hnn);
                float h = (1.f - z) * nn + z * __half2float(h_old[b * H_ + jg]);
                __half hh = __float2half_rn(h);
                h_new[b * H_ + jg] = hh;
                hs[((size_t)b * S_ + s) * H_ + jg] = hh;
            }
        }
    }
}

// ---------------------------------------------------------------------------
constexpr int SMEM_A_  = 3 * (128 + 128) * 40 * 2;  //  61440 B (phase A, BK=32)
constexpr int SMEM_C   = 3 * (128 + 128) * 56 * 2;  //  86016 B (phase C, 2 CTAs/SM)
constexpr int SMEM_REC = 5 * (32 + 48) * 56 * 2;    //  44800 B (recurrence, BK=48)
constexpr int C_GRID   = 296;                       // 2 CTAs x 148 SMs

extern "C" void kernel_launch(void* const* d_in, const int* in_sizes, int n_in,
                              void* d_out, int out_size) {
    const int*   tgt  = (const int*)  d_in[0];
    const float* sv   = (const float*)d_in[1];
    const float* emb  = (const float*)d_in[2];
    const float* Wih  = (const float*)d_in[3];
    const float* Whh  = (const float*)d_in[4];
    const float* bih  = (const float*)d_in[5];
    const float* bhh  = (const float*)d_in[6];
    const float* Wout = (const float*)d_in[7];
    const float* bout = (const float*)d_in[8];
    float* out = (float*)d_out;

    cudaFuncSetAttribute(gemm_f16<128, 128, 32, 32, 64, 0, 3, 0>,
                         cudaFuncAttributeMaxDynamicSharedMemorySize, SMEM_A_);
    cudaFuncSetAttribute(gemm_f16<128, 128, 48, 32, 64, 0, 3, 1>,
                         cudaFuncAttributeMaxDynamicSharedMemorySize, SMEM_C);
    cudaFuncSetAttribute(gemm_f16<32, 48, 48, 16, 24, 1, 5, 0>,
                         cudaFuncAttributeMaxDynamicSharedMemorySize, SMEM_REC);

    __half *p_emb, *p_hs, *p_h0, *p_h1, *p_wih, *p_whh, *p_wout;
    float *p_xg, *p_bih, *p_bhh;
    cudaGetSymbolAddress((void**)&p_emb, g_emb);
    cudaGetSymbolAddress((void**)&p_xg,  g_xg);
    cudaGetSymbolAddress((void**)&p_hs,  g_hs);
    cudaGetSymbolAddress((void**)&p_h0,  g_h0);
    cudaGetSymbolAddress((void**)&p_h1,  g_h1);
    cudaGetSymbolAddress((void**)&p_wih, g_wih);
    cudaGetSymbolAddress((void**)&p_whh, g_whh);
    cudaGetSymbolAddress((void**)&p_wout, g_wout);
    cudaGetSymbolAddress((void**)&p_bih, g_bih);
    cudaGetSymbolAddress((void**)&p_bhh, g_bhh);

    // Pre-pass: weight reorder / fp16 conversion
    prep_whh<<<2048, 256>>>(Whh);
    prep_wih_bias<<<2048, 256>>>(Wih, bih, bhh);
    prep_wout<<<4096, 256>>>(Wout);

    // Gather + h0
    gather_init_kernel<<<(M_ * EK_ + 255) / 256, 256>>>(tgt, emb, sv);

    // Phase A: x_gates (interleaved, fp32) = emb @ W_ih'^T + b_ih'  (K=320)
    {
        dim3 grid(M_ / 128, (G_ + 127) / 128);
        gemm_f16<128, 128, 32, 32, 64, 0, 3, 0><<<grid, 256, SMEM_A_>>>(
            p_emb, p_wih, p_bih, p_xg, M_, G_, EK_,
            nullptr, nullptr, nullptr, nullptr, 0);
    }

    // Phase B: 64 launched GRU steps, 150 CTAs, BK=48, 5 stages
    __half* hcur = p_h0;
    __half* hnext = p_h1;
    for (int s = 0; s < S_; s++) {
        dim3 grid(1, G_ / 48);  // 150 blocks
        gemm_f16<32, 48, 48, 16, 24, 1, 5, 0><<<grid, 128, SMEM_REC>>>(
            hcur, p_whh, p_bhh, nullptr, B_, G_, H_,
            p_xg, hcur, hnext, p_hs, s);
        __half* t = hcur; hcur = hnext; hnext = t;
    }

    // Phase C: logits = hs @ W_out^T + b_out
    // Persistent tile loop: 296 CTAs sweep 16x157 tiles (m-fastest order)
    {
        gemm_f16<128, 128, 48, 32, 64, 0, 3, 1><<<C_GRID, 256, SMEM_C>>>(
            p_hs, p_wout, bout, out, M_, V_, H_,
            nullptr, nullptr, nullptr, nullptr, 0);
    }
}

// round 16
// speedup vs baseline: 1.0836x; 1.0836x over previous
#include <cuda_runtime.h>
#include <cuda_fp16.h>
#include <cstdint>

// Problem constants
constexpr int V_ = 20000;
constexpr int E_ = 300;
constexpr int EK_ = 320;      // E padded to BK multiple (zero-filled)
constexpr int H_ = 2400;
constexpr int B_ = 32;
constexpr int S_ = 64;
constexpr int M_ = B_ * S_;   // 2048
constexpr int G_ = 3 * H_;    // 7200

static_assert(EK_ % 32 == 0, "phase A K tiling");
static_assert(H_ % 48 == 0, "recurrence + phase C K tiling (BK=48)");
static_assert(E_ % 4 == 0 && H_ % 4 == 0 && EK_ % 4 == 0, "vectorized preps");

// Scratch (static device globals; no runtime allocation)
__device__ __half g_emb[(size_t)M_ * EK_];
__device__ float  g_xg[(size_t)M_ * G_];
__device__ __half g_hs[(size_t)M_ * H_];   // layout [b][s][H]
__device__ __half g_h0[B_ * H_];
__device__ __half g_h1[B_ * H_];
__device__ __half g_wih[(size_t)G_ * EK_];
__device__ __half g_whh[(size_t)G_ * H_];
__device__ __half g_wout[(size_t)V_ * H_];
__device__ float  g_bih[G_];
__device__ float  g_bhh[G_];

// ---------------------------------------------------------------------------
#define MMA_F16(c, a, b)                                                      \
    asm volatile(                                                             \
        "mma.sync.aligned.m16n8k16.row.col.f32.f16.f16.f32 "                  \
        "{%0,%1,%2,%3}, {%4,%5,%6,%7}, {%8,%9}, {%0,%1,%2,%3};\n"             \
        : "+f"((c)[0]), "+f"((c)[1]), "+f"((c)[2]), "+f"((c)[3])              \
        : "r"((a)[0]), "r"((a)[1]), "r"((a)[2]), "r"((a)[3]),                 \
          "r"((b)[0]), "r"((b)[1]))

__device__ __forceinline__ void ldsm_x4(uint32_t& r0, uint32_t& r1,
                                        uint32_t& r2, uint32_t& r3, uint32_t a) {
    asm volatile("ldmatrix.sync.aligned.m8n8.x4.shared.b16 {%0,%1,%2,%3}, [%4];"
                 : "=r"(r0), "=r"(r1), "=r"(r2), "=r"(r3) : "r"(a));
}
__device__ __forceinline__ void ldsm_x2(uint32_t& r0, uint32_t& r1, uint32_t a) {
    asm volatile("ldmatrix.sync.aligned.m8n8.x2.shared.b16 {%0,%1}, [%2];"
                 : "=r"(r0), "=r"(r1) : "r"(a));
}

__device__ __forceinline__ void cvt4_store(__half* dst, float4 v) {
    __half2* d2 = reinterpret_cast<__half2*>(dst);
    d2[0] = __floats2half2_rn(v.x, v.y);
    d2[1] = __floats2half2_rn(v.z, v.w);
}

// ---------------------------------------------------------------------------
// Pre-pass kernels (vectorized: float4 loads, half2 stores; same rounding)
// ---------------------------------------------------------------------------
__global__ void prep_whh(const float* __restrict__ Whh) {
    constexpr int HQ = H_ / 4;
    size_t n = (size_t)G_ * HQ;
    for (size_t i = (size_t)blockIdx.x * blockDim.x + threadIdx.x; i < n;
         i += (size_t)gridDim.x * blockDim.x) {
        int np = (int)(i / HQ);
        int kq = (int)(i - (size_t)np * HQ);
        int j = np / 3, g = np % 3;
        float4 v = *reinterpret_cast<const float4*>(
            Whh + (size_t)(g * H_ + j) * H_ + 4 * kq);
        cvt4_store(g_whh + (size_t)np * H_ + 4 * kq, v);
    }
}
__global__ void prep_wih_bias(const float* __restrict__ Wih,
                              const float* __restrict__ bih,
                              const float* __restrict__ bhh) {
    constexpr int EQ = EK_ / 4;
    size_t n = (size_t)G_ * EQ;
    for (size_t i = (size_t)blockIdx.x * blockDim.x + threadIdx.x; i < n;
         i += (size_t)gridDim.x * blockDim.x) {
        int np = (int)(i / EQ);
        int kq = (int)(i - (size_t)np * EQ);
        int k = 4 * kq;
        int j = np / 3, g = np % 3;
        float4 v = make_float4(0.f, 0.f, 0.f, 0.f);
        if (k < E_)  // E_ % 4 == 0: groups never straddle the boundary
            v = *reinterpret_cast<const float4*>(
                Wih + (size_t)(g * H_ + j) * E_ + k);
        cvt4_store(g_wih + (size_t)np * EK_ + k, v);
    }
    int t = blockIdx.x * blockDim.x + threadIdx.x;
    if (t < G_) {
        int j = t / 3, g = t % 3;
        g_bih[t] = bih[g * H_ + j];
        g_bhh[t] = bhh[g * H_ + j];
    }
}
__global__ void prep_wout(const float* __restrict__ Wout) {
    size_t n = (size_t)V_ * H_ / 4;
    const float4* src = reinterpret_cast<const float4*>(Wout);
    for (size_t i = (size_t)blockIdx.x * blockDim.x + threadIdx.x; i < n;
         i += (size_t)gridDim.x * blockDim.x)
        cvt4_store(g_wout + 4 * i, src[i]);
}

__global__ void gather_init_kernel(const int* __restrict__ tgt,
                                   const float* __restrict__ emb_table,
                                   const float* __restrict__ sentence_vec) {
    constexpr int EQ = EK_ / 4;
    int idx = blockIdx.x * blockDim.x + threadIdx.x;
    if (idx < M_ * EQ) {
        int m = idx / EQ;
        int e = 4 * (idx - m * EQ);
        float4 v = make_float4(0.f, 0.f, 0.f, 0.f);
        if (e < E_)  // E_ % 4 == 0: no straddle
            v = *reinterpret_cast<const float4*>(
                emb_table + (size_t)tgt[m] * E_ + e);
        cvt4_store(g_emb + (size_t)m * EK_ + e, v);
    }
    if (idx < B_ * H_ / 4) {
        float4 v = reinterpret_cast<const float4*>(sentence_vec)[idx];
        cvt4_store(g_h0 + 4 * idx, v);
    }
}

// ---------------------------------------------------------------------------
// fp16 pipelined GEMM (HMMA m16n8k16 + ldmatrix).
//   C[m,n] = sum_k A[m,k]*B[n,k]  (+bias / fused GRU epilogue)
// EPI 0: C = acc + bias (fp32 out).  EPI 1: fused GRU update (BM=32).
// Requires K % BK == 0.
// ---------------------------------------------------------------------------
template <int BM, int BN, int BK, int WM, int WN, int EPI, int STAGES>
__global__ void __launch_bounds__((BM / WM) * (BN / WN) * 32)
gemm_f16(const __half* __restrict__ A, const __half* __restrict__ Bmat,
         const float* __restrict__ bias, float* __restrict__ C,
         int M, int N, int K,
         const float* __restrict__ xg, const __half* __restrict__ h_old,
         __half* __restrict__ h_new, __half* __restrict__ hs, int s) {
    constexpr int WARPS_M = BM / WM;
    constexpr int WARPS_N = BN / WN;
    constexpr int NT = WARPS_M * WARPS_N * 32;
    constexpr int MFRAG = WM / 16;
    constexpr int NFRAG = WN / 8;
    constexpr int LDH = BK + 8;
    constexpr int A_ST = BM * LDH;
    constexpr int B_ST = BN * LDH;
    constexpr int ST = A_ST + B_ST;

    extern __shared__ __half smbuf[];

    const int tid = threadIdx.x;
    const int warp = tid >> 5, lane = tid & 31;
    const int gr = lane >> 2, gc = lane & 3;
    const int wm = (warp % WARPS_M) * WM;
    const int wn = (warp / WARPS_M) * WN;
    const int bm0 = blockIdx.x * BM;
    const int bn0 = blockIdx.y * BN;

    const uint32_t sbase = (uint32_t)__cvta_generic_to_shared(smbuf);

    const int sub = lane >> 3, lr = lane & 7;
    const int a_off = ((sub & 1) * 8 + lr) * LDH + (sub >> 1) * 8;
    const int b_off = ((sub >> 1) * 8 + lr) * LDH + (sub & 1) * 8;
    const int b2_off = ((lane & 15) >> 3) * 8 + (lr)*LDH;

    const int T = K / BK;

    auto load_tile = [&](int stage, int t) {
        const uint32_t sA = sbase + stage * ST * 2;
        const uint32_t sB = sA + A_ST * 2;
        const int k0 = t * BK;
        constexpr int CHR = BK / 8;
        constexpr int CHA = BM * CHR;
#pragma unroll
        for (int c = tid; c < CHA; c += NT) {
            int row = c / CHR, ch = c % CHR;
            uint32_t dst = sA + (row * LDH + ch * 8) * 2;
            const __half* src = A + (size_t)(bm0 + row) * K + k0 + ch * 8;
            asm volatile("cp.async.cg.shared.global [%0], [%1], 16;\n" ::
                         "r"(dst), "l"(src));
        }
        constexpr int CHB = BN * CHR;
#pragma unroll
        for (int c = tid; c < CHB; c += NT) {
            int row = c / CHR, ch = c % CHR;
            int gn = bn0 + row;
            uint32_t dst = sB + (row * LDH + ch * 8) * 2;
            const __half* src = Bmat + (size_t)gn * K + k0 + ch * 8;
            int bytes = (gn < N) ? 16 : 0;
            asm volatile("cp.async.cg.shared.global [%0], [%1], 16, %2;\n" ::
                         "r"(dst), "l"(src), "r"(bytes));
        }
        asm volatile("cp.async.commit_group;\n");
    };

    float acc[MFRAG][NFRAG][4];
#pragma unroll
    for (int i = 0; i < MFRAG; i++)
#pragma unroll
        for (int j = 0; j < NFRAG; j++)
#pragma unroll
            for (int r = 0; r < 4; r++) acc[i][j][r] = 0.f;

    const int npre = (STAGES - 1 < T) ? STAGES - 1 : T;
    for (int t = 0; t < npre; t++) load_tile(t, t);

    for (int t = 0; t < T; t++) {
        asm volatile("cp.async.wait_group %0;\n" ::"n"(STAGES - 2));
        __syncthreads();
        if (t + STAGES - 1 < T) {
            load_tile((t + STAGES - 1) % STAGES, t + STAGES - 1);
        } else {
            asm volatile("cp.async.commit_group;\n");
        }
        const uint32_t sA = sbase + (t % STAGES) * ST * 2;
        const uint32_t sB = sA + A_ST * 2;
#pragma unroll
        for (int kk = 0; kk < BK; kk += 16) {
            uint32_t af[MFRAG][4];
#pragma unroll
            for (int i = 0; i < MFRAG; i++)
                ldsm_x4(af[i][0], af[i][1], af[i][2], af[i][3],
                        sA + ((wm + i * 16) * LDH + kk + a_off) * 2);
            uint32_t bf[NFRAG][2];
#pragma unroll
            for (int j = 0; j + 1 < NFRAG; j += 2)
                ldsm_x4(bf[j][0], bf[j][1], bf[j + 1][0], bf[j + 1][1],
                        sB + ((wn + j * 8) * LDH + kk + b_off) * 2);
            if (NFRAG & 1)
                ldsm_x2(bf[NFRAG - 1][0], bf[NFRAG - 1][1],
                        sB + ((wn + (NFRAG - 1) * 8) * LDH + kk + b2_off) * 2);
#pragma unroll
            for (int i = 0; i < MFRAG; i++)
#pragma unroll
                for (int j = 0; j < NFRAG; j++) MMA_F16(acc[i][j], af[i], bf[j]);
        }
    }

    if (EPI == 0) {
#pragma unroll
        for (int i = 0; i < MFRAG; i++)
#pragma unroll
            for (int j = 0; j < NFRAG; j++) {
                int n = bn0 + wn + j * 8 + gc * 2;
#pragma unroll
                for (int half_ = 0; half_ < 2; half_++) {
                    int m = bm0 + wm + i * 16 + gr + half_ * 8;
                    float v0 = acc[i][j][half_ * 2 + 0];
                    float v1 = acc[i][j][half_ * 2 + 1];
                    if (n < N)     C[(size_t)m * N + n]     = v0 + bias[n];
                    if (n + 1 < N) C[(size_t)m * N + n + 1] = v1 + bias[n + 1];
                }
            }
    } else {
        // Fused GRU update. BM=32 (batch), BN=48 (16 hidden units x 3 gates,
        // interleaved r,z,n). acc -> smem -> per-(b,j) update.
        __syncthreads();
        float* hg = (float*)smbuf;   // 32x48 floats (aliases stages, post-sync)
#pragma unroll
        for (int i = 0; i < MFRAG; i++)
#pragma unroll
            for (int j = 0; j < NFRAG; j++) {
                int m0 = wm + i * 16 + gr;
                int n0 = wn + j * 8 + gc * 2;
                hg[m0 * BN + n0]           = acc[i][j][0];
                hg[m0 * BN + n0 + 1]       = acc[i][j][1];
                hg[(m0 + 8) * BN + n0]     = acc[i][j][2];
                hg[(m0 + 8) * BN + n0 + 1] = acc[i][j][3];
            }
        __syncthreads();
        const int jbase = bn0 / 3;
        for (int it = tid; it < B_ * (BN / 3); it += NT) {
            int b = it / (BN / 3);
            int lj = it % (BN / 3);
            int jg = jbase + lj;
            float hr = hg[b * BN + 3 * lj + 0] + bias[bn0 + 3 * lj + 0];
            float hz = hg[b * BN + 3 * lj + 1] + bias[bn0 + 3 * lj + 1];
            float hnn = hg[b * BN + 3 * lj + 2] + bias[bn0 + 3 * lj + 2];
            const float* xrow = xg + (size_t)(b * S_ + s) * G_ + bn0 + 3 * lj;
            float xr = xrow[0], xz = xrow[1], xn = xrow[2];
            float r = 1.f / (1.f + expf(-(xr + hr)));
            float z = 1.f / (1.f + expf(-(xz + hz)));
            float nn = tanhf(xn + r * hnn);
            float h = (1.f - z) * nn + z * __half2float(h_old[b * H_ + jg]);
            __half hh = __float2half_rn(h);
            h_new[b * H_ + jg] = hh;
            hs[((size_t)b * S_ + s) * H_ + jg] = hh;
        }
    }
}

// ---------------------------------------------------------------------------
constexpr int SMEM_A_  = 3 * (128 + 128) * 40 * 2;  //  61440 B (phase A, BK=32)
constexpr int SMEM_C   = 3 * (128 + 128) * 56 * 2;  //  86016 B (phase C, 2 CTAs/SM)
constexpr int SMEM_REC = 5 * (32 + 48) * 56 * 2;    //  44800 B (recurrence, BK=48)

extern "C" void kernel_launch(void* const* d_in, const int* in_sizes, int n_in,
                              void* d_out, int out_size) {
    const int*   tgt  = (const int*)  d_in[0];
    const float* sv   = (const float*)d_in[1];
    const float* emb  = (const float*)d_in[2];
    const float* Wih  = (const float*)d_in[3];
    const float* Whh  = (const float*)d_in[4];
    const float* bih  = (const float*)d_in[5];
    const float* bhh  = (const float*)d_in[6];
    const float* Wout = (const float*)d_in[7];
    const float* bout = (const float*)d_in[8];
    float* out = (float*)d_out;

    cudaFuncSetAttribute(gemm_f16<128, 128, 32, 32, 64, 0, 3>,
                         cudaFuncAttributeMaxDynamicSharedMemorySize, SMEM_A_);
    cudaFuncSetAttribute(gemm_f16<128, 128, 48, 32, 64, 0, 3>,
                         cudaFuncAttributeMaxDynamicSharedMemorySize, SMEM_C);
    cudaFuncSetAttribute(gemm_f16<32, 48, 48, 16, 24, 1, 5>,
                         cudaFuncAttributeMaxDynamicSharedMemorySize, SMEM_REC);

    __half *p_emb, *p_hs, *p_h0, *p_h1, *p_wih, *p_whh, *p_wout;
    float *p_xg, *p_bih, *p_bhh;
    cudaGetSymbolAddress((void**)&p_emb, g_emb);
    cudaGetSymbolAddress((void**)&p_xg,  g_xg);
    cudaGetSymbolAddress((void**)&p_hs,  g_hs);
    cudaGetSymbolAddress((void**)&p_h0,  g_h0);
    cudaGetSymbolAddress((void**)&p_h1,  g_h1);
    cudaGetSymbolAddress((void**)&p_wih, g_wih);
    cudaGetSymbolAddress((void**)&p_whh, g_whh);
    cudaGetSymbolAddress((void**)&p_wout, g_wout);
    cudaGetSymbolAddress((void**)&p_bih, g_bih);
    cudaGetSymbolAddress((void**)&p_bhh, g_bhh);

    // Pre-pass: weight reorder / fp16 conversion (vectorized)
    prep_whh<<<2048, 256>>>(Whh);
    prep_wih_bias<<<2048, 256>>>(Wih, bih, bhh);
    prep_wout<<<2048, 256>>>(Wout);

    // Gather + h0 (vectorized)
    gather_init_kernel<<<(M_ * (EK_ / 4) + 255) / 256, 256>>>(tgt, emb, sv);

    // Phase A: x_gates (interleaved, fp32) = emb @ W_ih'^T + b_ih'  (K=320)
    {
        dim3 grid(M_ / 128, (G_ + 127) / 128);
        gemm_f16<128, 128, 32, 32, 64, 0, 3><<<grid, 256, SMEM_A_>>>(
            p_emb, p_wih, p_bih, p_xg, M_, G_, EK_,
            nullptr, nullptr, nullptr, nullptr, 0);
    }

    // Phase B: 64 launched GRU steps, 150 CTAs, BK=48, 5 stages
    __half* hcur = p_h0;
    __half* hnext = p_h1;
    for (int s = 0; s < S_; s++) {
        dim3 grid(1, G_ / 48);  // 150 blocks
        gemm_f16<32, 48, 48, 16, 24, 1, 5><<<grid, 128, SMEM_REC>>>(
            hcur, p_whh, p_bhh, nullptr, B_, G_, H_,
            p_xg, hcur, hnext, p_hs, s);
        __half* t = hcur; hcur = hnext; hnext = t;
    }

    // Phase C: logits = hs @ W_out^T + b_out
    // 128x128 tile, BK=48, 3 stages, 256 threads -> 2 CTAs/SM (R14 config)
    {
        dim3 grid(M_ / 128, (V_ + 127) / 128);  // 16 x 157
        gemm_f16<128, 128, 48, 32, 64, 0, 3><<<grid, 256, SMEM_C>>>(
            p_hs, p_wout, bout, out, M_, V_, H_,
            nullptr, nullptr, nullptr, nullptr, 0);
    }
}

// round 17
// speedup vs baseline: 1.0857x; 1.0019x over previous
#include <cuda_runtime.h>
#include <cuda_fp16.h>
#include <cstdint>

// Problem constants
constexpr int V_ = 20000;
constexpr int E_ = 300;
constexpr int EK_ = 320;      // E padded to BK multiple (zero-filled)
constexpr int H_ = 2400;
constexpr int B_ = 32;
constexpr int S_ = 64;
constexpr int M_ = B_ * S_;   // 2048
constexpr int G_ = 3 * H_;    // 7200

static_assert(EK_ % 32 == 0, "phase A K tiling");
static_assert(H_ % 48 == 0, "recurrence + phase C K tiling (BK=48)");
static_assert(E_ % 4 == 0 && H_ % 4 == 0 && EK_ % 4 == 0, "vectorized preps");

// Scratch (static device globals; no runtime allocation)
__device__ __half g_emb[(size_t)M_ * EK_];
__device__ float  g_xg[(size_t)M_ * G_];
__device__ __half g_hs[(size_t)M_ * H_];   // layout [b][s][H]
__device__ __half g_h0[B_ * H_];
__device__ __half g_h1[B_ * H_];
__device__ __half g_wih[(size_t)G_ * EK_];
__device__ __half g_whh[(size_t)G_ * H_];
__device__ __half g_wout[(size_t)V_ * H_];
__device__ float  g_bih[G_];
__device__ float  g_bhh[G_];

// ---------------------------------------------------------------------------
#define MMA_F16(c, a, b)                                                      \
    asm volatile(                                                             \
        "mma.sync.aligned.m16n8k16.row.col.f32.f16.f16.f32 "                  \
        "{%0,%1,%2,%3}, {%4,%5,%6,%7}, {%8,%9}, {%0,%1,%2,%3};\n"             \
        : "+f"((c)[0]), "+f"((c)[1]), "+f"((c)[2]), "+f"((c)[3])              \
        : "r"((a)[0]), "r"((a)[1]), "r"((a)[2]), "r"((a)[3]),                 \
          "r"((b)[0]), "r"((b)[1]))

__device__ __forceinline__ void ldsm_x4(uint32_t& r0, uint32_t& r1,
                                        uint32_t& r2, uint32_t& r3, uint32_t a) {
    asm volatile("ldmatrix.sync.aligned.m8n8.x4.shared.b16 {%0,%1,%2,%3}, [%4];"
                 : "=r"(r0), "=r"(r1), "=r"(r2), "=r"(r3) : "r"(a));
}
__device__ __forceinline__ void ldsm_x2(uint32_t& r0, uint32_t& r1, uint32_t a) {
    asm volatile("ldmatrix.sync.aligned.m8n8.x2.shared.b16 {%0,%1}, [%2];"
                 : "=r"(r0), "=r"(r1) : "r"(a));
}

__device__ __forceinline__ void cvt4_store(__half* dst, float4 v) {
    __half2* d2 = reinterpret_cast<__half2*>(dst);
    d2[0] = __floats2half2_rn(v.x, v.y);
    d2[1] = __floats2half2_rn(v.z, v.w);
}

// ---------------------------------------------------------------------------
// Pre-pass kernels (vectorized: float4 loads, half2 stores; same rounding)
// ---------------------------------------------------------------------------
__global__ void prep_whh(const float* __restrict__ Whh) {
    constexpr int HQ = H_ / 4;
    size_t n = (size_t)G_ * HQ;
    for (size_t i = (size_t)blockIdx.x * blockDim.x + threadIdx.x; i < n;
         i += (size_t)gridDim.x * blockDim.x) {
        int np = (int)(i / HQ);
        int kq = (int)(i - (size_t)np * HQ);
        int j = np / 3, g = np % 3;
        float4 v = *reinterpret_cast<const float4*>(
            Whh + (size_t)(g * H_ + j) * H_ + 4 * kq);
        cvt4_store(g_whh + (size_t)np * H_ + 4 * kq, v);
    }
}
__global__ void prep_wih_bias(const float* __restrict__ Wih,
                              const float* __restrict__ bih,
                              const float* __restrict__ bhh) {
    constexpr int EQ = EK_ / 4;
    size_t n = (size_t)G_ * EQ;
    for (size_t i = (size_t)blockIdx.x * blockDim.x + threadIdx.x; i < n;
         i += (size_t)gridDim.x * blockDim.x) {
        int np = (int)(i / EQ);
        int kq = (int)(i - (size_t)np * EQ);
        int k = 4 * kq;
        int j = np / 3, g = np % 3;
        float4 v = make_float4(0.f, 0.f, 0.f, 0.f);
        if (k < E_)  // E_ % 4 == 0: groups never straddle the boundary
            v = *reinterpret_cast<const float4*>(
                Wih + (size_t)(g * H_ + j) * E_ + k);
        cvt4_store(g_wih + (size_t)np * EK_ + k, v);
    }
    int t = blockIdx.x * blockDim.x + threadIdx.x;
    if (t < G_) {
        int j = t / 3, g = t % 3;
        g_bih[t] = bih[g * H_ + j];
        g_bhh[t] = bhh[g * H_ + j];
    }
}
__global__ void prep_wout(const float* __restrict__ Wout) {
    size_t n = (size_t)V_ * H_ / 4;
    const float4* src = reinterpret_cast<const float4*>(Wout);
    for (size_t i = (size_t)blockIdx.x * blockDim.x + threadIdx.x; i < n;
         i += (size_t)gridDim.x * blockDim.x)
        cvt4_store(g_wout + 4 * i, src[i]);
}

__global__ void gather_init_kernel(const int* __restrict__ tgt,
                                   const float* __restrict__ emb_table,
                                   const float* __restrict__ sentence_vec) {
    constexpr int EQ = EK_ / 4;
    int idx = blockIdx.x * blockDim.x + threadIdx.x;
    if (idx < M_ * EQ) {
        int m = idx / EQ;
        int e = 4 * (idx - m * EQ);
        float4 v = make_float4(0.f, 0.f, 0.f, 0.f);
        if (e < E_)  // E_ % 4 == 0: no straddle
            v = *reinterpret_cast<const float4*>(
                emb_table + (size_t)tgt[m] * E_ + e);
        cvt4_store(g_emb + (size_t)m * EK_ + e, v);
    }
    if (idx < B_ * H_ / 4) {
        float4 v = reinterpret_cast<const float4*>(sentence_vec)[idx];
        cvt4_store(g_h0 + 4 * idx, v);
    }
}

// ---------------------------------------------------------------------------
// fp16 pipelined GEMM (HMMA m16n8k16 + ldmatrix).
//   C[m,n] = sum_k A[m,k]*B[n,k]  (+bias / fused GRU epilogue)
// EPI 0: C = acc + bias (fp32 out).  EPI 1: fused GRU update (BM=32).
// Requires K % BK == 0.
// ---------------------------------------------------------------------------
template <int BM, int BN, int BK, int WM, int WN, int EPI, int STAGES>
__global__ void __launch_bounds__((BM / WM) * (BN / WN) * 32)
gemm_f16(const __half* __restrict__ A, const __half* __restrict__ Bmat,
         const float* __restrict__ bias, float* __restrict__ C,
         int M, int N, int K,
         const float* __restrict__ xg, const __half* __restrict__ h_old,
         __half* __restrict__ h_new, __half* __restrict__ hs, int s) {
    constexpr int WARPS_M = BM / WM;
    constexpr int WARPS_N = BN / WN;
    constexpr int NT = WARPS_M * WARPS_N * 32;
    constexpr int MFRAG = WM / 16;
    constexpr int NFRAG = WN / 8;
    constexpr int LDH = BK + 8;
    constexpr int A_ST = BM * LDH;
    constexpr int B_ST = BN * LDH;
    constexpr int ST = A_ST + B_ST;

    extern __shared__ __half smbuf[];

    const int tid = threadIdx.x;
    const int warp = tid >> 5, lane = tid & 31;
    const int gr = lane >> 2, gc = lane & 3;
    const int wm = (warp % WARPS_M) * WM;
    const int wn = (warp / WARPS_M) * WN;
    const int bm0 = blockIdx.x * BM;
    const int bn0 = blockIdx.y * BN;

    const uint32_t sbase = (uint32_t)__cvta_generic_to_shared(smbuf);

    const int sub = lane >> 3, lr = lane & 7;
    const int a_off = ((sub & 1) * 8 + lr) * LDH + (sub >> 1) * 8;
    const int b_off = ((sub >> 1) * 8 + lr) * LDH + (sub & 1) * 8;
    const int b2_off = ((lane & 15) >> 3) * 8 + (lr)*LDH;

    const int T = K / BK;

    auto load_tile = [&](int stage, int t) {
        const uint32_t sA = sbase + stage * ST * 2;
        const uint32_t sB = sA + A_ST * 2;
        const int k0 = t * BK;
        constexpr int CHR = BK / 8;
        constexpr int CHA = BM * CHR;
#pragma unroll
        for (int c = tid; c < CHA; c += NT) {
            int row = c / CHR, ch = c % CHR;
            uint32_t dst = sA + (row * LDH + ch * 8) * 2;
            const __half* src = A + (size_t)(bm0 + row) * K + k0 + ch * 8;
            asm volatile("cp.async.cg.shared.global [%0], [%1], 16;\n" ::
                         "r"(dst), "l"(src));
        }
        constexpr int CHB = BN * CHR;
#pragma unroll
        for (int c = tid; c < CHB; c += NT) {
            int row = c / CHR, ch = c % CHR;
            int gn = bn0 + row;
            uint32_t dst = sB + (row * LDH + ch * 8) * 2;
            const __half* src = Bmat + (size_t)gn * K + k0 + ch * 8;
            int bytes = (gn < N) ? 16 : 0;
            asm volatile("cp.async.cg.shared.global [%0], [%1], 16, %2;\n" ::
                         "r"(dst), "l"(src), "r"(bytes));
        }
        asm volatile("cp.async.commit_group;\n");
    };

    float acc[MFRAG][NFRAG][4];
#pragma unroll
    for (int i = 0; i < MFRAG; i++)
#pragma unroll
        for (int j = 0; j < NFRAG; j++)
#pragma unroll
            for (int r = 0; r < 4; r++) acc[i][j][r] = 0.f;

    const int npre = (STAGES - 1 < T) ? STAGES - 1 : T;
    for (int t = 0; t < npre; t++) load_tile(t, t);

    for (int t = 0; t < T; t++) {
        asm volatile("cp.async.wait_group %0;\n" ::"n"(STAGES - 2));
        __syncthreads();
        if (t + STAGES - 1 < T) {
            load_tile((t + STAGES - 1) % STAGES, t + STAGES - 1);
        } else {
            asm volatile("cp.async.commit_group;\n");
        }
        const uint32_t sA = sbase + (t % STAGES) * ST * 2;
        const uint32_t sB = sA + A_ST * 2;
#pragma unroll
        for (int kk = 0; kk < BK; kk += 16) {
            uint32_t af[MFRAG][4];
#pragma unroll
            for (int i = 0; i < MFRAG; i++)
                ldsm_x4(af[i][0], af[i][1], af[i][2], af[i][3],
                        sA + ((wm + i * 16) * LDH + kk + a_off) * 2);
            uint32_t bf[NFRAG][2];
#pragma unroll
            for (int j = 0; j + 1 < NFRAG; j += 2)
                ldsm_x4(bf[j][0], bf[j][1], bf[j + 1][0], bf[j + 1][1],
                        sB + ((wn + j * 8) * LDH + kk + b_off) * 2);
            if (NFRAG & 1)
                ldsm_x2(bf[NFRAG - 1][0], bf[NFRAG - 1][1],
                        sB + ((wn + (NFRAG - 1) * 8) * LDH + kk + b2_off) * 2);
#pragma unroll
            for (int i = 0; i < MFRAG; i++)
#pragma unroll
                for (int j = 0; j < NFRAG; j++) MMA_F16(acc[i][j], af[i], bf[j]);
        }
    }

    if (EPI == 0) {
#pragma unroll
        for (int i = 0; i < MFRAG; i++)
#pragma unroll
            for (int j = 0; j < NFRAG; j++) {
                int n = bn0 + wn + j * 8 + gc * 2;
#pragma unroll
                for (int half_ = 0; half_ < 2; half_++) {
                    int m = bm0 + wm + i * 16 + gr + half_ * 8;
                    float v0 = acc[i][j][half_ * 2 + 0];
                    float v1 = acc[i][j][half_ * 2 + 1];
                    if (n < N)     C[(size_t)m * N + n]     = v0 + bias[n];
                    if (n + 1 < N) C[(size_t)m * N + n + 1] = v1 + bias[n + 1];
                }
            }
    } else {
        // Fused GRU update. BM=32 (batch), BN=48 (16 hidden units x 3 gates,
        // interleaved r,z,n). acc -> smem -> per-(b,j) update.
        __syncthreads();
        float* hg = (float*)smbuf;   // 32x48 floats (aliases stages, post-sync)
#pragma unroll
        for (int i = 0; i < MFRAG; i++)
#pragma unroll
            for (int j = 0; j < NFRAG; j++) {
                int m0 = wm + i * 16 + gr;
                int n0 = wn + j * 8 + gc * 2;
                hg[m0 * BN + n0]           = acc[i][j][0];
                hg[m0 * BN + n0 + 1]       = acc[i][j][1];
                hg[(m0 + 8) * BN + n0]     = acc[i][j][2];
                hg[(m0 + 8) * BN + n0 + 1] = acc[i][j][3];
            }
        __syncthreads();
        const int jbase = bn0 / 3;
        for (int it = tid; it < B_ * (BN / 3); it += NT) {
            int b = it / (BN / 3);
            int lj = it % (BN / 3);
            int jg = jbase + lj;
            float hr = hg[b * BN + 3 * lj + 0] + bias[bn0 + 3 * lj + 0];
            float hz = hg[b * BN + 3 * lj + 1] + bias[bn0 + 3 * lj + 1];
            float hnn = hg[b * BN + 3 * lj + 2] + bias[bn0 + 3 * lj + 2];
            const float* xrow = xg + (size_t)(b * S_ + s) * G_ + bn0 + 3 * lj;
            float xr = xrow[0], xz = xrow[1], xn = xrow[2];
            float r = 1.f / (1.f + expf(-(xr + hr)));
            float z = 1.f / (1.f + expf(-(xz + hz)));
            float nn = tanhf(xn + r * hnn);
            float h = (1.f - z) * nn + z * __half2float(h_old[b * H_ + jg]);
            __half hh = __float2half_rn(h);
            h_new[b * H_ + jg] = hh;
            hs[((size_t)b * S_ + s) * H_ + jg] = hh;
        }
    }
}

// ---------------------------------------------------------------------------
constexpr int SMEM_A_  = 3 * (128 + 128) * 40 * 2;  //  61440 B (phase A, BK=32)
constexpr int SMEM_C   = 4 * (128 + 128) * 56 * 2;  // 114688 B (phase C, 4 st, 2 CTAs/SM)
constexpr int SMEM_REC = 5 * (32 + 48) * 56 * 2;    //  44800 B (recurrence, BK=48)

extern "C" void kernel_launch(void* const* d_in, const int* in_sizes, int n_in,
                              void* d_out, int out_size) {
    const int*   tgt  = (const int*)  d_in[0];
    const float* sv   = (const float*)d_in[1];
    const float* emb  = (const float*)d_in[2];
    const float* Wih  = (const float*)d_in[3];
    const float* Whh  = (const float*)d_in[4];
    const float* bih  = (const float*)d_in[5];
    const float* bhh  = (const float*)d_in[6];
    const float* Wout = (const float*)d_in[7];
    const float* bout = (const float*)d_in[8];
    float* out = (float*)d_out;

    // One-time stream/event resources (same work every call)
    static cudaStream_t s2 = nullptr;
    static cudaEvent_t ev_fork, ev_join;
    static bool init_ok = []() {
        if (cudaStreamCreateWithFlags(&s2, cudaStreamNonBlocking) != cudaSuccess)
            return false;
        if (cudaEventCreateWithFlags(&ev_fork, cudaEventDisableTiming) != cudaSuccess)
            return false;
        if (cudaEventCreateWithFlags(&ev_join, cudaEventDisableTiming) != cudaSuccess)
            return false;
        return true;
    }();
    const bool ovl = init_ok;
    cudaStream_t cs = ovl ? s2 : (cudaStream_t)0;

    cudaFuncSetAttribute(gemm_f16<128, 128, 32, 32, 64, 0, 3>,
                         cudaFuncAttributeMaxDynamicSharedMemorySize, SMEM_A_);
    cudaFuncSetAttribute(gemm_f16<128, 128, 48, 32, 64, 0, 4>,
                         cudaFuncAttributeMaxDynamicSharedMemorySize, SMEM_C);
    cudaFuncSetAttribute(gemm_f16<32, 48, 48, 16, 24, 1, 5>,
                         cudaFuncAttributeMaxDynamicSharedMemorySize, SMEM_REC);

    __half *p_emb, *p_hs, *p_h0, *p_h1, *p_wih, *p_whh, *p_wout;
    float *p_xg, *p_bih, *p_bhh;
    cudaGetSymbolAddress((void**)&p_emb, g_emb);
    cudaGetSymbolAddress((void**)&p_xg,  g_xg);
    cudaGetSymbolAddress((void**)&p_hs,  g_hs);
    cudaGetSymbolAddress((void**)&p_h0,  g_h0);
    cudaGetSymbolAddress((void**)&p_h1,  g_h1);
    cudaGetSymbolAddress((void**)&p_wih, g_wih);
    cudaGetSymbolAddress((void**)&p_whh, g_whh);
    cudaGetSymbolAddress((void**)&p_wout, g_wout);
    cudaGetSymbolAddress((void**)&p_bih, g_bih);
    cudaGetSymbolAddress((void**)&p_bhh, g_bhh);

    // Fork: prep_wout (only needed by phase C) runs on the side stream,
    // overlapping the other preps, phase A and phase B.
    if (ovl) {
        cudaEventRecord(ev_fork, 0);
        cudaStreamWaitEvent(cs, ev_fork, 0);
    }
    prep_wout<<<2048, 256, 0, cs>>>(Wout);
    if (ovl) cudaEventRecord(ev_join, cs);

    // Main stream: remaining preps + gather (vectorized)
    prep_whh<<<2048, 256>>>(Whh);
    prep_wih_bias<<<2048, 256>>>(Wih, bih, bhh);
    gather_init_kernel<<<(M_ * (EK_ / 4) + 255) / 256, 256>>>(tgt, emb, sv);

    // Phase A: x_gates (interleaved, fp32) = emb @ W_ih'^T + b_ih'  (K=320)
    {
        dim3 grid(M_ / 128, (G_ + 127) / 128);
        gemm_f16<128, 128, 32, 32, 64, 0, 3><<<grid, 256, SMEM_A_>>>(
            p_emb, p_wih, p_bih, p_xg, M_, G_, EK_,
            nullptr, nullptr, nullptr, nullptr, 0);
    }

    // Phase B: 64 launched GRU steps, 150 CTAs, BK=48, 5 stages
    __half* hcur = p_h0;
    __half* hnext = p_h1;
    for (int s = 0; s < S_; s++) {
        dim3 grid(1, G_ / 48);  // 150 blocks
        gemm_f16<32, 48, 48, 16, 24, 1, 5><<<grid, 128, SMEM_REC>>>(
            hcur, p_whh, p_bhh, nullptr, B_, G_, H_,
            p_xg, hcur, hnext, p_hs, s);
        __half* t = hcur; hcur = hnext; hnext = t;
    }

    // Join: phase C needs g_wout
    if (ovl) cudaStreamWaitEvent(0, ev_join, 0);

    // Phase C: logits = hs @ W_out^T + b_out
    // 128x128 tile, BK=48, 4 stages, 256 threads -> 2 CTAs/SM
    {
        dim3 grid(M_ / 128, (V_ + 127) / 128);  // 16 x 157
        gemm_f16<128, 128, 48, 32, 64, 0, 4><<<grid, 256, SMEM_C>>>(
            p_hs, p_wout, bout, out, M_, V_, H_,
            nullptr, nullptr, nullptr, nullptr, 0);
    }
}